// round 11
// baseline (speedup 1.0000x reference)
#include <cuda_runtime.h>

#define B_ 128
#define N_ 1024
#define E_ 16384
#define ENTITY_ 100000
#define HID_ 100
#define G3 300

// Scratch (static __device__ per harness rules; no runtime allocation)
__device__ float g_seq[B_ * N_ * HID_];      // spmm(emb[nbr])      (52MB)
__device__ float g_GX[B_ * N_ * G3];         // seq @ Wc + bc       (157MB)
__device__ float g_Wc[HID_ * G3];            // gcn_w @ w_ih^T  [100][300] k-major
__device__ float g_bc[G3];                   // w_ih @ gcn_b + b_ih
__device__ int   g_soff[B_ * (N_ + 1)];
__device__ int   g_scol[B_ * E_];
__device__ float g_sval[B_ * E_];

typedef unsigned long long u64;
typedef unsigned int u32;

__device__ __forceinline__ void ffma2(u64 &acc, u64 a, u64 b) {
    asm("fma.rn.f32x2 %0, %1, %2, %0;" : "+l"(acc) : "l"(a), "l"(b));
}
__device__ __forceinline__ float sum2(u64 v) {
    float lo, hi; asm("mov.b64 {%0, %1}, %2;" : "=f"(lo), "=f"(hi) : "l"(v)); return lo + hi;
}
__device__ __forceinline__ void cp4(void* s, const void* g) {
    unsigned a = (unsigned)__cvta_generic_to_shared(s);
    asm volatile("cp.async.ca.shared.global [%0], [%1], 4;" :: "r"(a), "l"(g));
}
__device__ __forceinline__ u32 f2tf(float x) {
    u32 r; asm("cvt.rna.tf32.f32 %0, %1;" : "=r"(r) : "f"(x)); return r;
}
__device__ __forceinline__ float tanhapx(float x) {
    float r; asm("tanh.approx.f32 %0, %1;" : "=f"(r) : "f"(x)); return r;
}
__device__ __forceinline__ void mma1688(float c[4], u32 a0, u32 a1, u32 a2, u32 a3,
                                        u32 b0, u32 b1) {
    asm("mma.sync.aligned.m16n8k8.row.col.f32.tf32.tf32.f32 "
        "{%0,%1,%2,%3}, {%4,%5,%6,%7}, {%8,%9}, {%0,%1,%2,%3};"
        : "+f"(c[0]), "+f"(c[1]), "+f"(c[2]), "+f"(c[3])
        : "r"(a0), "r"(a1), "r"(a2), "r"(a3), "r"(b0), "r"(b1));
}

// ---------------------------------------------------------------------------
// K0: fold the GCN weights through the GRU input projection (fp32).
// Wc[e][j] = sum_h gcn_w[e][h] * w_ih[j][h]      (shape [100, 300], k-major)
// bc[j]    = sum_h gcn_b[h]   * w_ih[j][h] + b_ih[j]
// Block e < 100 computes Wc row e; block 100 computes bc. 300 threads.
// ---------------------------------------------------------------------------
__global__ __launch_bounds__(G3) void k0_fold(const float* __restrict__ gcn_w,
                                              const float* __restrict__ gcn_b,
                                              const float* __restrict__ w_ih,
                                              const float* __restrict__ b_ih) {
    __shared__ float xs[HID_];
    int j = threadIdx.x;
    int e = blockIdx.x;
    const float* src = (e < HID_) ? (gcn_w + e * HID_) : gcn_b;
    if (j < HID_) xs[j] = src[j];
    __syncthreads();
    float acc = (e < HID_) ? 0.f : b_ih[j];
    const float* wr = w_ih + j * HID_;
    #pragma unroll
    for (int h = 0; h < HID_; h++) acc += xs[h] * wr[h];
    if (e < HID_) g_Wc[e * G3 + j] = acc;
    else          g_bc[j] = acc;
}

// ---------------------------------------------------------------------------
// tf32 GEMM: out[M x NOUT] = X[M x 100] @ W^T (+ bias if HASB)   [R9 — proven]
// M-tile = 128 rows; 512 threads = 16 warps (4 m-pos x 4 n-groups); W staged
// once per block; k-PAIRED smem layout -> all fragment loads are LDS.64.
// ---------------------------------------------------------------------------
#define KP 104

__device__ __forceinline__ int kidx(int k) {   // paired index within a row
    return ((k >> 3) << 3) + ((k & 3) << 1) + ((k & 7) >> 2);
}

template<int NP, int NFR, int NOUT, bool TRANSW, bool USE_GSEQ, bool HASB>
__global__ __launch_bounds__(512) void gemm_tf32(const float* __restrict__ Xparam,
                                                 const float* __restrict__ Wg,
                                                 const float* __restrict__ bias,
                                                 int Mtotal, int ntiles) {
    extern __shared__ u32 smem[];
    u32* Ws = smem;                                   // NP * KP
    u32* Xs = smem + NP * KP;                         // 128 * KP
    float* bs = (float*)(smem + NP * KP + 128 * KP);  // NP

    const float* X = USE_GSEQ ? (const float*)g_seq : Xparam;
    float* out = USE_GSEQ ? (float*)g_GX : nullptr;

    int tid = threadIdx.x;
    int w = tid >> 5, lane = tid & 31;
    int mw = w & 3, nw = w >> 2;
    int g = lane >> 2, tig = lane & 3;
    int colbase = nw * NFR * 8;

    for (int i = tid; i < NP * KP; i += 512) {
        int n = i / KP, k = i % KP;
        float v = 0.f;
        if (n < NOUT && k < HID_)
            v = TRANSW ? Wg[k * NOUT + n] : Wg[n * HID_ + k];
        Ws[n * KP + kidx(k)] = f2tf(v);
    }
    for (int i = tid; i < NP; i += 512)
        bs[i] = (HASB && i < NOUT) ? bias[i] : 0.f;
    __syncthreads();

    for (int tile = blockIdx.x; tile < ntiles; tile += gridDim.x) {
        __syncthreads();
        for (int i = tid; i < 128 * 26; i += 512) {
            int m = i / 26, c = i % 26;
            u32* rowp = Xs + m * KP;
            if (c < 25) {
                int row = tile * 128 + m;
                float4 v = make_float4(0.f, 0.f, 0.f, 0.f);
                if (row < Mtotal) v = ((const float4*)X)[(size_t)row * 25 + c];
                int base = ((c >> 1) << 3) + (c & 1);
                rowp[base]     = f2tf(v.x);
                rowp[base + 2] = f2tf(v.y);
                rowp[base + 4] = f2tf(v.z);
                rowp[base + 6] = f2tf(v.w);
            } else {
                rowp[97] = 0u; rowp[99] = 0u; rowp[101] = 0u; rowp[103] = 0u;
            }
        }
        __syncthreads();

        float c[2][NFR][4];
        #pragma unroll
        for (int mb = 0; mb < 2; mb++)
            #pragma unroll
            for (int f = 0; f < NFR; f++) {
                c[mb][f][0] = 0.f; c[mb][f][1] = 0.f;
                c[mb][f][2] = 0.f; c[mb][f][3] = 0.f;
            }

        const u32* Xb0 = Xs + (mw * 16) * KP;
        const u32* Xb1 = Xs + (64 + mw * 16) * KP;
        #pragma unroll
        for (int ks = 0; ks < 13; ks++) {
            int k0 = ks * 8 + 2 * tig;
            uint2 a00 = *(const uint2*)&Xb0[g * KP + k0];
            uint2 a01 = *(const uint2*)&Xb0[(g + 8) * KP + k0];
            uint2 a10 = *(const uint2*)&Xb1[g * KP + k0];
            uint2 a11 = *(const uint2*)&Xb1[(g + 8) * KP + k0];
            #pragma unroll
            for (int f = 0; f < NFR; f++) {
                uint2 pb = *(const uint2*)&Ws[(colbase + 8 * f + g) * KP + k0];
                mma1688(c[0][f], a00.x, a01.x, a00.y, a01.y, pb.x, pb.y);
                mma1688(c[1][f], a10.x, a11.x, a10.y, a11.y, pb.x, pb.y);
            }
        }

        #pragma unroll
        for (int mb = 0; mb < 2; mb++) {
            int r0 = tile * 128 + mb * 64 + mw * 16 + g;
            #pragma unroll
            for (int f = 0; f < NFR; f++) {
                int col = colbase + 8 * f + 2 * tig;
                if (r0 < Mtotal) {
                    if (col < NOUT)     out[(size_t)r0 * NOUT + col]     = c[mb][f][0] + bs[col];
                    if (col + 1 < NOUT) out[(size_t)r0 * NOUT + col + 1] = c[mb][f][1] + bs[col + 1];
                }
                if (r0 + 8 < Mtotal) {
                    if (col < NOUT)     out[(size_t)(r0 + 8) * NOUT + col]     = c[mb][f][2] + bs[col];
                    if (col + 1 < NOUT) out[(size_t)(r0 + 8) * NOUT + col + 1] = c[mb][f][3] + bs[col + 1];
                }
            }
        }
    }
}

#define K4_SMEM ((320 * KP + 128 * KP) * 4 + 320 * 4)

// ---------------------------------------------------------------------------
// K2: per-batch counting sort of edges by row (histogram + scan + scatter)
// ---------------------------------------------------------------------------
__global__ __launch_bounds__(1024) void k2_sort(const int* __restrict__ row,
                                                const int* __restrict__ col,
                                                const float* __restrict__ val) {
    __shared__ int bins[N_];
    __shared__ int sA[N_];
    int b = blockIdx.x, tid = threadIdx.x;
    bins[tid] = 0;
    __syncthreads();
    const int* rb = row + b * E_;
    const int* cb = col + b * E_;
    const float* vb = val + b * E_;
    for (int e = tid; e < E_; e += 1024) atomicAdd(&bins[rb[e]], 1);
    __syncthreads();
    int cnt = bins[tid];
    sA[tid] = cnt;
    __syncthreads();
    for (int off = 1; off < N_; off <<= 1) {
        int t = (tid >= off) ? sA[tid - off] : 0;
        __syncthreads();
        sA[tid] += t;
        __syncthreads();
    }
    int excl = sA[tid] - cnt;
    g_soff[b * (N_ + 1) + tid] = excl;
    if (tid == 0) g_soff[b * (N_ + 1) + N_] = E_;
    bins[tid] = excl;
    __syncthreads();
    for (int e = tid; e < E_; e += 1024) {
        int r = rb[e];
        int pos = atomicAdd(&bins[r], 1);
        g_scol[b * E_ + pos] = cb[e];
        g_sval[b * E_ + pos] = vb[e];
    }
}

// ---------------------------------------------------------------------------
// K3: seq[b,r,:] = sum_e val * emb[neighbors[b, col_e], :]   (pure spmm; the
// GCN weights + bias are folded into K4's Wc/bc). One warp per (b, row);
// lane l<25 owns dims [4l,4l+4) via LDG.128; 4-edge unroll.
// ---------------------------------------------------------------------------
__global__ __launch_bounds__(256) void k3_agg(const float* __restrict__ emb,
                                              const int* __restrict__ nbr) {
    int b = blockIdx.x;
    int rbase = blockIdx.y * 64;
    int warp = threadIdx.x >> 5, lane = threadIdx.x & 31;
    const int* sc = g_scol + b * E_;
    const float* sv = g_sval + b * E_;
    const int* nb = nbr + b * N_;
    bool ld = lane < 25;
    for (int r = rbase + warp; r < rbase + 64; r += 8) {
        int beg = g_soff[b * (N_ + 1) + r], end = g_soff[b * (N_ + 1) + r + 1];
        float4 acc0 = make_float4(0.f, 0.f, 0.f, 0.f);
        float4 acc1 = make_float4(0.f, 0.f, 0.f, 0.f);
        for (int ch = beg; ch < end; ch += 32) {
            int e = ch + lane;
            int cc = 0; float vv = 0.f;
            if (e < end) { cc = sc[e]; vv = sv[e]; }
            int ent = nb[cc];
            int cnt = min(32, end - ch);
            int i = 0;
            for (; i + 3 < cnt; i += 4) {
                int e0 = __shfl_sync(0xffffffffu, ent, i);
                int e1 = __shfl_sync(0xffffffffu, ent, i + 1);
                int e2 = __shfl_sync(0xffffffffu, ent, i + 2);
                int e3 = __shfl_sync(0xffffffffu, ent, i + 3);
                float v0 = __shfl_sync(0xffffffffu, vv, i);
                float v1 = __shfl_sync(0xffffffffu, vv, i + 1);
                float v2 = __shfl_sync(0xffffffffu, vv, i + 2);
                float v3 = __shfl_sync(0xffffffffu, vv, i + 3);
                if (ld) {
                    float4 x0 = *(const float4*)(emb + (size_t)e0 * HID_ + 4 * lane);
                    float4 x1 = *(const float4*)(emb + (size_t)e1 * HID_ + 4 * lane);
                    float4 x2 = *(const float4*)(emb + (size_t)e2 * HID_ + 4 * lane);
                    float4 x3 = *(const float4*)(emb + (size_t)e3 * HID_ + 4 * lane);
                    acc0.x += v0 * x0.x; acc0.y += v0 * x0.y; acc0.z += v0 * x0.z; acc0.w += v0 * x0.w;
                    acc1.x += v1 * x1.x; acc1.y += v1 * x1.y; acc1.z += v1 * x1.z; acc1.w += v1 * x1.w;
                    acc0.x += v2 * x2.x; acc0.y += v2 * x2.y; acc0.z += v2 * x2.z; acc0.w += v2 * x2.w;
                    acc1.x += v3 * x3.x; acc1.y += v3 * x3.y; acc1.z += v3 * x3.z; acc1.w += v3 * x3.w;
                }
            }
            for (; i < cnt; i++) {
                int e0 = __shfl_sync(0xffffffffu, ent, i);
                float v0 = __shfl_sync(0xffffffffu, vv, i);
                if (ld) {
                    float4 x0 = *(const float4*)(emb + (size_t)e0 * HID_ + 4 * lane);
                    acc0.x += v0 * x0.x; acc0.y += v0 * x0.y; acc0.z += v0 * x0.z; acc0.w += v0 * x0.w;
                }
            }
        }
        if (ld) {
            float4 o;
            o.x = acc0.x + acc1.x;
            o.y = acc0.y + acc1.y;
            o.z = acc0.z + acc1.z;
            o.w = acc0.w + acc1.w;
            *(float4*)(g_seq + (size_t)(b * N_ + r) * HID_ + 4 * lane) = o;
        }
    }
}

// ---------------------------------------------------------------------------
// K5: GRU recurrence, one block per batch; k-SPLIT x2 (R10); HW tanh.approx.
// ---------------------------------------------------------------------------
__global__ __launch_bounds__(608) void k5_gru(const float* __restrict__ w_hh,
                                              const float* __restrict__ b_hh,
                                              const float* __restrict__ fc1_w,
                                              const float* __restrict__ fc1_b,
                                              float* __restrict__ out) {
    __shared__ __align__(16) float hbuf[2][128];   // [0..99] h, [100..103] zero pad
    __shared__ float ps[2][304];
    __shared__ float ring[8][G3];
    int b = blockIdx.x, tid = threadIdx.x;
    int q = tid / 304;          // k-half
    int j = tid % 304;          // gate index, <300 active
    bool act = j < G3;
    u64 w2[26];
    if (act) {
        #pragma unroll
        for (int p = 0; p < 26; p++) {
            int k = 52 * q + 2 * p;
            w2[p] = (k + 1 < HID_) ? *(const u64*)(w_hh + j * HID_ + k) : 0ull;
        }
    }
    float br = 0.f, bz = 0.f, bn = 0.f;
    if (tid < HID_) {
        br = b_hh[tid]; bz = b_hh[HID_ + tid]; bn = b_hh[2 * HID_ + tid];
    }
    if (tid < 128) { hbuf[0][tid] = 0.f; hbuf[1][tid] = 0.f; }
    const float* gxb = g_GX + (size_t)b * N_ * G3;
    #pragma unroll
    for (int p = 0; p < 4; p++) {
        if (tid < G3) cp4(&ring[p][tid], gxb + p * G3 + tid);
        asm volatile("cp.async.commit_group;");
    }
    for (int t = 0; t < N_; t++) {
        asm volatile("cp.async.wait_group 3;");
        __syncthreads();                     // stage-t ring + new h visible
        int pf = t + 4;
        if (tid < G3 && pf < N_) cp4(&ring[pf & 7][tid], gxb + (size_t)pf * G3 + tid);
        asm volatile("cp.async.commit_group;");
        const float* hc = hbuf[t & 1];
        if (act) {
            const ulonglong2* hp = (const ulonglong2*)(hc + 52 * q);
            u64 a0 = 0, a1 = 0, a2 = 0, a3 = 0;
            #pragma unroll
            for (int cc = 0; cc < 13; cc++) {
                ulonglong2 hv = hp[cc];
                if (cc & 1) { ffma2(a2, w2[2 * cc], hv.x); ffma2(a3, w2[2 * cc + 1], hv.y); }
                else        { ffma2(a0, w2[2 * cc], hv.x); ffma2(a1, w2[2 * cc + 1], hv.y); }
            }
            ps[q][j] = sum2(a0) + sum2(a1) + sum2(a2) + sum2(a3);
        }
        __syncthreads();                     // partials ready
        if (tid < HID_) {
            int st = t & 7;
            float gxr = ring[st][tid], gxz = ring[st][HID_ + tid], gxn = ring[st][2 * HID_ + tid];
            float hr = ps[0][tid] + ps[1][tid] + br;
            float hz = ps[0][HID_ + tid] + ps[1][HID_ + tid] + bz;
            float hn = ps[0][2 * HID_ + tid] + ps[1][2 * HID_ + tid] + bn;
            float r = 0.5f * tanhapx(0.5f * (gxr + hr)) + 0.5f;
            float z = 0.5f * tanhapx(0.5f * (gxz + hz)) + 0.5f;
            float n = tanhapx(gxn + r * hn);
            hbuf[(t + 1) & 1][tid] = (1.f - z) * n + z * hc[tid];
        }
    }
    __syncthreads();
    if (tid < HID_) {
        const float* hf = hbuf[0];           // t=1023 wrote buffer 0
        float acc = fc1_b[tid];
        const float* wr = fc1_w + tid * HID_;
        #pragma unroll
        for (int k = 0; k < HID_; k++) acc += hf[k] * wr[k];
        out[b * HID_ + tid] = fmaxf(acc, 0.f);
    }
}

// ---------------------------------------------------------------------------
extern "C" void kernel_launch(void* const* d_in, const int* in_sizes, int n_in,
                              void* d_out, int out_size) {
    const int*   neighbors = (const int*)d_in[0];
    const int*   adj_row   = (const int*)d_in[1];
    const int*   adj_col   = (const int*)d_in[2];
    const float* adj_val   = (const float*)d_in[3];
    const float* emb       = (const float*)d_in[4];
    const float* gcn_w     = (const float*)d_in[5];
    const float* gcn_b     = (const float*)d_in[6];
    const float* w_ih      = (const float*)d_in[7];
    const float* w_hh      = (const float*)d_in[8];
    const float* b_ih      = (const float*)d_in[9];
    const float* b_hh      = (const float*)d_in[10];
    const float* fc1_w     = (const float*)d_in[11];
    const float* fc1_b     = (const float*)d_in[12];
    float* out = (float*)d_out;

    // Device-symbol addresses for the folded weights (host query; capture-safe)
    void* pWc = nullptr; void* pbc = nullptr;
    cudaGetSymbolAddress(&pWc, g_Wc);
    cudaGetSymbolAddress(&pbc, g_bc);

    cudaFuncSetAttribute(gemm_tf32<320, 10, 300, true, true, true>,
                         cudaFuncAttributeMaxDynamicSharedMemorySize, K4_SMEM);

    // K0: fold gcn_w/gcn_b through w_ih/b_ih  -> g_Wc, g_bc
    k0_fold<<<HID_ + 1, G3>>>(gcn_w, gcn_b, w_ih, b_ih);
    // K2: sort edges by row
    k2_sort<<<B_, 1024>>>(adj_row, adj_col, adj_val);
    // K3: pure spmm over raw embeddings
    k3_agg <<<dim3(B_, 16), 256>>>(emb, neighbors);
    // K4: GX = seq @ Wc + bc   (Wc is [100][300] k-major -> TRANSW path)
    gemm_tf32<320, 10, 300, true, true, true><<<148, 512, K4_SMEM>>>(
        nullptr, (const float*)pWc, (const float*)pbc, B_ * N_, (B_ * N_ + 127) / 128);
    // K5: GRU recurrence + fused FC
    k5_gru <<<B_, 608>>>(w_hh, b_hh, fc1_w, fc1_b, out);
}

// round 12
// speedup vs baseline: 1.5981x; 1.5981x over previous
#include <cuda_runtime.h>

#define B_ 128
#define N_ 1024
#define E_ 16384
#define ENTITY_ 100000
#define HID_ 100
#define G3 300

// Scratch (static __device__ per harness rules; no runtime allocation)
__device__ float g_seq[B_ * N_ * HID_];      // spmm(emb[nbr])      (52MB)
__device__ float g_GX[B_ * N_ * G3];         // seq @ Wc + bc       (157MB)
__device__ float g_Wc[HID_ * G3];            // gcn_w @ w_ih^T  [100][300] k-major
__device__ float g_bc[G3];                   // w_ih @ gcn_b + b_ih
__device__ int   g_soff[B_ * (N_ + 1)];
__device__ int   g_scol[B_ * E_];
__device__ float g_sval[B_ * E_];

typedef unsigned long long u64;
typedef unsigned int u32;

__device__ __forceinline__ void ffma2(u64 &acc, u64 a, u64 b) {
    asm("fma.rn.f32x2 %0, %1, %2, %0;" : "+l"(acc) : "l"(a), "l"(b));
}
__device__ __forceinline__ float sum2(u64 v) {
    float lo, hi; asm("mov.b64 {%0, %1}, %2;" : "=f"(lo), "=f"(hi) : "l"(v)); return lo + hi;
}
__device__ __forceinline__ void cp4(void* s, const void* g) {
    unsigned a = (unsigned)__cvta_generic_to_shared(s);
    asm volatile("cp.async.ca.shared.global [%0], [%1], 4;" :: "r"(a), "l"(g));
}
__device__ __forceinline__ u32 f2tf(float x) {
    u32 r; asm("cvt.rna.tf32.f32 %0, %1;" : "=r"(r) : "f"(x)); return r;
}
__device__ __forceinline__ float tanhapx(float x) {
    float r; asm("tanh.approx.f32 %0, %1;" : "=f"(r) : "f"(x)); return r;
}
__device__ __forceinline__ void mma1688(float c[4], u32 a0, u32 a1, u32 a2, u32 a3,
                                        u32 b0, u32 b1) {
    asm("mma.sync.aligned.m16n8k8.row.col.f32.tf32.tf32.f32 "
        "{%0,%1,%2,%3}, {%4,%5,%6,%7}, {%8,%9}, {%0,%1,%2,%3};"
        : "+f"(c[0]), "+f"(c[1]), "+f"(c[2]), "+f"(c[3])
        : "r"(a0), "r"(a1), "r"(a2), "r"(a3), "r"(b0), "r"(b1));
}

// ---------------------------------------------------------------------------
// K0: fold the GCN weights through the GRU input projection (fp32).
// Wc[e][j] = sum_h gcn_w[e][h] * w_ih[j][h]      ([100, 300], k-major)
// bc[j]    = sum_h gcn_b[h]   * w_ih[j][h] + b_ih[j]
// ---------------------------------------------------------------------------
__global__ __launch_bounds__(G3) void k0_fold(const float* __restrict__ gcn_w,
                                              const float* __restrict__ gcn_b,
                                              const float* __restrict__ w_ih,
                                              const float* __restrict__ b_ih) {
    __shared__ float xs[HID_];
    int j = threadIdx.x;
    int e = blockIdx.x;
    const float* src = (e < HID_) ? (gcn_w + e * HID_) : gcn_b;
    if (j < HID_) xs[j] = src[j];
    __syncthreads();
    float acc = (e < HID_) ? 0.f : b_ih[j];
    const float* wr = w_ih + j * HID_;
    #pragma unroll
    for (int h = 0; h < HID_; h++) acc += xs[h] * wr[h];
    if (e < HID_) g_Wc[e * G3 + j] = acc;
    else          g_bc[j] = acc;
}

// ---------------------------------------------------------------------------
// K4: tf32 GEMM  g_GX[M x 300] = g_seq[M x 100] @ Wc (+ bc)   [R9 machinery]
// M-tile = 128 rows; 512 threads = 16 warps (4 m-pos x 4 n-groups); W staged
// once per block; k-PAIRED smem layout -> all fragment loads are LDS.64.
// ---------------------------------------------------------------------------
#define KP 104

__device__ __forceinline__ int kidx(int k) {   // paired index within a row
    return ((k >> 3) << 3) + ((k & 3) << 1) + ((k & 7) >> 2);
}

#define NP4 320
#define NFR4 10

__global__ __launch_bounds__(512) void k4_gx(const float* __restrict__ Wg,
                                             const float* __restrict__ bias,
                                             int Mtotal, int ntiles) {
    extern __shared__ u32 smem[];
    u32* Ws = smem;                                    // NP4 * KP
    u32* Xs = smem + NP4 * KP;                         // 128 * KP
    float* bs = (float*)(smem + NP4 * KP + 128 * KP);  // NP4

    const float* X = (const float*)g_seq;
    float* out = (float*)g_GX;

    int tid = threadIdx.x;
    int w = tid >> 5, lane = tid & 31;
    int mw = w & 3, nw = w >> 2;
    int g = lane >> 2, tig = lane & 3;
    int colbase = nw * NFR4 * 8;

    for (int i = tid; i < NP4 * KP; i += 512) {
        int n = i / KP, k = i % KP;
        float v = (n < G3 && k < HID_) ? Wg[k * G3 + n] : 0.f;   // Wc is k-major
        Ws[n * KP + kidx(k)] = f2tf(v);
    }
    for (int i = tid; i < NP4; i += 512)
        bs[i] = (i < G3) ? bias[i] : 0.f;
    __syncthreads();

    for (int tile = blockIdx.x; tile < ntiles; tile += gridDim.x) {
        __syncthreads();
        for (int i = tid; i < 128 * 26; i += 512) {
            int m = i / 26, c = i % 26;
            u32* rowp = Xs + m * KP;
            if (c < 25) {
                int row = tile * 128 + m;
                float4 v = make_float4(0.f, 0.f, 0.f, 0.f);
                if (row < Mtotal) v = ((const float4*)X)[(size_t)row * 25 + c];
                int base = ((c >> 1) << 3) + (c & 1);
                rowp[base]     = f2tf(v.x);
                rowp[base + 2] = f2tf(v.y);
                rowp[base + 4] = f2tf(v.z);
                rowp[base + 6] = f2tf(v.w);
            } else {
                rowp[97] = 0u; rowp[99] = 0u; rowp[101] = 0u; rowp[103] = 0u;
            }
        }
        __syncthreads();

        float c[2][NFR4][4];
        #pragma unroll
        for (int mb = 0; mb < 2; mb++)
            #pragma unroll
            for (int f = 0; f < NFR4; f++) {
                c[mb][f][0] = 0.f; c[mb][f][1] = 0.f;
                c[mb][f][2] = 0.f; c[mb][f][3] = 0.f;
            }

        const u32* Xb0 = Xs + (mw * 16) * KP;
        const u32* Xb1 = Xs + (64 + mw * 16) * KP;
        #pragma unroll
        for (int ks = 0; ks < 13; ks++) {
            int k0 = ks * 8 + 2 * tig;
            uint2 a00 = *(const uint2*)&Xb0[g * KP + k0];
            uint2 a01 = *(const uint2*)&Xb0[(g + 8) * KP + k0];
            uint2 a10 = *(const uint2*)&Xb1[g * KP + k0];
            uint2 a11 = *(const uint2*)&Xb1[(g + 8) * KP + k0];
            #pragma unroll
            for (int f = 0; f < NFR4; f++) {
                uint2 pb = *(const uint2*)&Ws[(colbase + 8 * f + g) * KP + k0];
                mma1688(c[0][f], a00.x, a01.x, a00.y, a01.y, pb.x, pb.y);
                mma1688(c[1][f], a10.x, a11.x, a10.y, a11.y, pb.x, pb.y);
            }
        }

        #pragma unroll
        for (int mb = 0; mb < 2; mb++) {
            int r0 = tile * 128 + mb * 64 + mw * 16 + g;
            #pragma unroll
            for (int f = 0; f < NFR4; f++) {
                int col = colbase + 8 * f + 2 * tig;
                if (r0 < Mtotal) {
                    if (col < G3)     out[(size_t)r0 * G3 + col]     = c[mb][f][0] + bs[col];
                    if (col + 1 < G3) out[(size_t)r0 * G3 + col + 1] = c[mb][f][1] + bs[col + 1];
                }
                if (r0 + 8 < Mtotal) {
                    if (col < G3)     out[(size_t)(r0 + 8) * G3 + col]     = c[mb][f][2] + bs[col];
                    if (col + 1 < G3) out[(size_t)(r0 + 8) * G3 + col + 1] = c[mb][f][3] + bs[col + 1];
                }
            }
        }
    }
}

#define K4_SMEM ((NP4 * KP + 128 * KP) * 4 + NP4 * 4)

// ---------------------------------------------------------------------------
// K2: per-batch counting sort of edges by row (histogram + scan + scatter)
// ---------------------------------------------------------------------------
__global__ __launch_bounds__(1024) void k2_sort(const int* __restrict__ row,
                                                const int* __restrict__ col,
                                                const float* __restrict__ val) {
    __shared__ int bins[N_];
    __shared__ int sA[N_];
    int b = blockIdx.x, tid = threadIdx.x;
    bins[tid] = 0;
    __syncthreads();
    const int* rb = row + b * E_;
    const int* cb = col + b * E_;
    const float* vb = val + b * E_;
    for (int e = tid; e < E_; e += 1024) atomicAdd(&bins[rb[e]], 1);
    __syncthreads();
    int cnt = bins[tid];
    sA[tid] = cnt;
    __syncthreads();
    for (int off = 1; off < N_; off <<= 1) {
        int t = (tid >= off) ? sA[tid - off] : 0;
        __syncthreads();
        sA[tid] += t;
        __syncthreads();
    }
    int excl = sA[tid] - cnt;
    g_soff[b * (N_ + 1) + tid] = excl;
    if (tid == 0) g_soff[b * (N_ + 1) + N_] = E_;
    bins[tid] = excl;
    __syncthreads();
    for (int e = tid; e < E_; e += 1024) {
        int r = rb[e];
        int pos = atomicAdd(&bins[r], 1);
        g_scol[b * E_ + pos] = cb[e];
        g_sval[b * E_ + pos] = vb[e];
    }
}

// ---------------------------------------------------------------------------
// K3: seq[b,r,:] = sum_e val * emb[neighbors[b, col_e], :]   (pure spmm; the
// GCN weights + bias are folded into K4's Wc/bc). One warp per (b, row);
// lane l<25 owns dims [4l,4l+4) via LDG.128; 4-edge unroll.
// ---------------------------------------------------------------------------
__global__ __launch_bounds__(256) void k3_agg(const float* __restrict__ emb,
                                              const int* __restrict__ nbr) {
    int b = blockIdx.x;
    int rbase = blockIdx.y * 64;
    int warp = threadIdx.x >> 5, lane = threadIdx.x & 31;
    const int* sc = g_scol + b * E_;
    const float* sv = g_sval + b * E_;
    const int* nb = nbr + b * N_;
    bool ld = lane < 25;
    for (int r = rbase + warp; r < rbase + 64; r += 8) {
        int beg = g_soff[b * (N_ + 1) + r], end = g_soff[b * (N_ + 1) + r + 1];
        float4 acc0 = make_float4(0.f, 0.f, 0.f, 0.f);
        float4 acc1 = make_float4(0.f, 0.f, 0.f, 0.f);
        for (int ch = beg; ch < end; ch += 32) {
            int e = ch + lane;
            int cc = 0; float vv = 0.f;
            if (e < end) { cc = sc[e]; vv = sv[e]; }
            int ent = nb[cc];
            int cnt = min(32, end - ch);
            int i = 0;
            for (; i + 3 < cnt; i += 4) {
                int e0 = __shfl_sync(0xffffffffu, ent, i);
                int e1 = __shfl_sync(0xffffffffu, ent, i + 1);
                int e2 = __shfl_sync(0xffffffffu, ent, i + 2);
                int e3 = __shfl_sync(0xffffffffu, ent, i + 3);
                float v0 = __shfl_sync(0xffffffffu, vv, i);
                float v1 = __shfl_sync(0xffffffffu, vv, i + 1);
                float v2 = __shfl_sync(0xffffffffu, vv, i + 2);
                float v3 = __shfl_sync(0xffffffffu, vv, i + 3);
                if (ld) {
                    float4 x0 = *(const float4*)(emb + (size_t)e0 * HID_ + 4 * lane);
                    float4 x1 = *(const float4*)(emb + (size_t)e1 * HID_ + 4 * lane);
                    float4 x2 = *(const float4*)(emb + (size_t)e2 * HID_ + 4 * lane);
                    float4 x3 = *(const float4*)(emb + (size_t)e3 * HID_ + 4 * lane);
                    acc0.x += v0 * x0.x; acc0.y += v0 * x0.y; acc0.z += v0 * x0.z; acc0.w += v0 * x0.w;
                    acc1.x += v1 * x1.x; acc1.y += v1 * x1.y; acc1.z += v1 * x1.z; acc1.w += v1 * x1.w;
                    acc0.x += v2 * x2.x; acc0.y += v2 * x2.y; acc0.z += v2 * x2.z; acc0.w += v2 * x2.w;
                    acc1.x += v3 * x3.x; acc1.y += v3 * x3.y; acc1.z += v3 * x3.z; acc1.w += v3 * x3.w;
                }
            }
            for (; i < cnt; i++) {
                int e0 = __shfl_sync(0xffffffffu, ent, i);
                float v0 = __shfl_sync(0xffffffffu, vv, i);
                if (ld) {
                    float4 x0 = *(const float4*)(emb + (size_t)e0 * HID_ + 4 * lane);
                    acc0.x += v0 * x0.x; acc0.y += v0 * x0.y; acc0.z += v0 * x0.z; acc0.w += v0 * x0.w;
                }
            }
        }
        if (ld) {
            float4 o;
            o.x = acc0.x + acc1.x;
            o.y = acc0.y + acc1.y;
            o.z = acc0.z + acc1.z;
            o.w = acc0.w + acc1.w;
            *(float4*)(g_seq + (size_t)(b * N_ + r) * HID_ + 4 * lane) = o;
        }
    }
}

// ---------------------------------------------------------------------------
// K5: GRU recurrence, one block per batch; k-SPLIT x2; HW tanh.approx.
// ---------------------------------------------------------------------------
__global__ __launch_bounds__(608) void k5_gru(const float* __restrict__ w_hh,
                                              const float* __restrict__ b_hh,
                                              const float* __restrict__ fc1_w,
                                              const float* __restrict__ fc1_b,
                                              float* __restrict__ out) {
    __shared__ __align__(16) float hbuf[2][128];   // [0..99] h, [100..103] zero pad
    __shared__ float ps[2][304];
    __shared__ float ring[8][G3];
    int b = blockIdx.x, tid = threadIdx.x;
    int q = tid / 304;          // k-half
    int j = tid % 304;          // gate index, <300 active
    bool act = j < G3;
    u64 w2[26];
    if (act) {
        #pragma unroll
        for (int p = 0; p < 26; p++) {
            int k = 52 * q + 2 * p;
            w2[p] = (k + 1 < HID_) ? *(const u64*)(w_hh + j * HID_ + k) : 0ull;
        }
    }
    float br = 0.f, bz = 0.f, bn = 0.f;
    if (tid < HID_) {
        br = b_hh[tid]; bz = b_hh[HID_ + tid]; bn = b_hh[2 * HID_ + tid];
    }
    if (tid < 128) { hbuf[0][tid] = 0.f; hbuf[1][tid] = 0.f; }
    const float* gxb = g_GX + (size_t)b * N_ * G3;
    #pragma unroll
    for (int p = 0; p < 4; p++) {
        if (tid < G3) cp4(&ring[p][tid], gxb + p * G3 + tid);
        asm volatile("cp.async.commit_group;");
    }
    for (int t = 0; t < N_; t++) {
        asm volatile("cp.async.wait_group 3;");
        __syncthreads();                     // stage-t ring + new h visible
        int pf = t + 4;
        if (tid < G3 && pf < N_) cp4(&ring[pf & 7][tid], gxb + (size_t)pf * G3 + tid);
        asm volatile("cp.async.commit_group;");
        const float* hc = hbuf[t & 1];
        if (act) {
            const ulonglong2* hp = (const ulonglong2*)(hc + 52 * q);
            u64 a0 = 0, a1 = 0, a2 = 0, a3 = 0;
            #pragma unroll
            for (int cc = 0; cc < 13; cc++) {
                ulonglong2 hv = hp[cc];
                if (cc & 1) { ffma2(a2, w2[2 * cc], hv.x); ffma2(a3, w2[2 * cc + 1], hv.y); }
                else        { ffma2(a0, w2[2 * cc], hv.x); ffma2(a1, w2[2 * cc + 1], hv.y); }
            }
            ps[q][j] = sum2(a0) + sum2(a1) + sum2(a2) + sum2(a3);
        }
        __syncthreads();                     // partials ready
        if (tid < HID_) {
            int st = t & 7;
            float gxr = ring[st][tid], gxz = ring[st][HID_ + tid], gxn = ring[st][2 * HID_ + tid];
            float hr = ps[0][tid] + ps[1][tid] + br;
            float hz = ps[0][HID_ + tid] + ps[1][HID_ + tid] + bz;
            float hn = ps[0][2 * HID_ + tid] + ps[1][2 * HID_ + tid] + bn;
            float r = 0.5f * tanhapx(0.5f * (gxr + hr)) + 0.5f;
            float z = 0.5f * tanhapx(0.5f * (gxz + hz)) + 0.5f;
            float n = tanhapx(gxn + r * hn);
            hbuf[(t + 1) & 1][tid] = (1.f - z) * n + z * hc[tid];
        }
    }
    __syncthreads();
    if (tid < HID_) {
        const float* hf = hbuf[0];           // t=1023 wrote buffer 0
        float acc = fc1_b[tid];
        const float* wr = fc1_w + tid * HID_;
        #pragma unroll
        for (int k = 0; k < HID_; k++) acc += hf[k] * wr[k];
        out[b * HID_ + tid] = fmaxf(acc, 0.f);
    }
}

// ---------------------------------------------------------------------------
extern "C" void kernel_launch(void* const* d_in, const int* in_sizes, int n_in,
                              void* d_out, int out_size) {
    const int*   neighbors = (const int*)d_in[0];
    const int*   adj_row   = (const int*)d_in[1];
    const int*   adj_col   = (const int*)d_in[2];
    const float* adj_val   = (const float*)d_in[3];
    const float* emb       = (const float*)d_in[4];
    const float* gcn_w     = (const float*)d_in[5];
    const float* gcn_b     = (const float*)d_in[6];
    const float* w_ih      = (const float*)d_in[7];
    const float* w_hh      = (const float*)d_in[8];
    const float* b_ih      = (const float*)d_in[9];
    const float* b_hh      = (const float*)d_in[10];
    const float* fc1_w     = (const float*)d_in[11];
    const float* fc1_b     = (const float*)d_in[12];
    float* out = (float*)d_out;

    // Device-symbol addresses for the folded weights (pure lookup; capture-safe)
    void* pWc = nullptr; void* pbc = nullptr;
    cudaGetSymbolAddress(&pWc, g_Wc);
    cudaGetSymbolAddress(&pbc, g_bc);

    cudaFuncSetAttribute(k4_gx, cudaFuncAttributeMaxDynamicSharedMemorySize, K4_SMEM);

    // K0: fold gcn_w/gcn_b through w_ih/b_ih  -> g_Wc, g_bc
    k0_fold<<<HID_ + 1, G3>>>(gcn_w, gcn_b, w_ih, b_ih);
    // K2: sort edges by row
    k2_sort<<<B_, 1024>>>(adj_row, adj_col, adj_val);
    // K3: pure spmm over raw embeddings
    k3_agg <<<dim3(B_, 16), 256>>>(emb, neighbors);
    // K4: GX = seq @ Wc + bc
    k4_gx  <<<148, 512, K4_SMEM>>>((const float*)pWc, (const float*)pbc,
                                   B_ * N_, (B_ * N_ + 127) / 128);
    // K5: GRU recurrence + fused FC
    k5_gru <<<B_, 608>>>(w_hh, b_hh, fc1_w, fc1_b, out);
}

// round 13
// speedup vs baseline: 1.6814x; 1.0521x over previous
#include <cuda_runtime.h>

#define B_ 128
#define N_ 1024
#define E_ 16384
#define ENTITY_ 100000
#define HID_ 100
#define G3 300

// Scratch (static __device__ per harness rules; no runtime allocation)
__device__ float g_seq[B_ * N_ * HID_];      // spmm(emb[nbr])      (52MB)
__device__ float g_Wc[HID_ * G3];            // gcn_w @ w_ih^T  [100][300] k-major
__device__ float g_bc[G3];                   // w_ih @ gcn_b + b_ih
__device__ int   g_soff[B_ * (N_ + 1)];
__device__ int   g_scol[B_ * E_];
__device__ float g_sval[B_ * E_];

typedef unsigned long long u64;
typedef unsigned int u32;

__device__ __forceinline__ void ffma2(u64 &acc, u64 a, u64 b) {
    asm("fma.rn.f32x2 %0, %1, %2, %0;" : "+l"(acc) : "l"(a), "l"(b));
}
__device__ __forceinline__ float sum2(u64 v) {
    float lo, hi; asm("mov.b64 {%0, %1}, %2;" : "=f"(lo), "=f"(hi) : "l"(v)); return lo + hi;
}
__device__ __forceinline__ u32 f2tf(float x) {
    u32 r; asm("cvt.rna.tf32.f32 %0, %1;" : "=r"(r) : "f"(x)); return r;
}
__device__ __forceinline__ float tanhapx(float x) {
    float r; asm("tanh.approx.f32 %0, %1;" : "=f"(r) : "f"(x)); return r;
}
__device__ __forceinline__ void mma1688(float c[4], u32 a0, u32 a1, u32 a2, u32 a3,
                                        u32 b0, u32 b1) {
    asm("mma.sync.aligned.m16n8k8.row.col.f32.tf32.tf32.f32 "
        "{%0,%1,%2,%3}, {%4,%5,%6,%7}, {%8,%9}, {%0,%1,%2,%3};"
        : "+f"(c[0]), "+f"(c[1]), "+f"(c[2]), "+f"(c[3])
        : "r"(a0), "r"(a1), "r"(a2), "r"(a3), "r"(b0), "r"(b1));
}

__device__ __forceinline__ int kidx(int k) {   // paired index within a 104-k row
    return ((k >> 3) << 3) + ((k & 3) << 1) + ((k & 7) >> 2);
}

// ---------------------------------------------------------------------------
// K0: fold the GCN weights through the GRU input projection (fp32).
// Wc[e][j] = sum_h gcn_w[e][h] * w_ih[j][h]      ([100, 300], k-major)
// bc[j]    = sum_h gcn_b[h]   * w_ih[j][h] + b_ih[j]
// ---------------------------------------------------------------------------
__global__ __launch_bounds__(G3) void k0_fold(const float* __restrict__ gcn_w,
                                              const float* __restrict__ gcn_b,
                                              const float* __restrict__ w_ih,
                                              const float* __restrict__ b_ih) {
    __shared__ float xs[HID_];
    int j = threadIdx.x;
    int e = blockIdx.x;
    const float* src = (e < HID_) ? (gcn_w + e * HID_) : gcn_b;
    if (j < HID_) xs[j] = src[j];
    __syncthreads();
    float acc = (e < HID_) ? 0.f : b_ih[j];
    const float* wr = w_ih + j * HID_;
    #pragma unroll
    for (int h = 0; h < HID_; h++) acc += xs[h] * wr[h];
    if (e < HID_) g_Wc[e * G3 + j] = acc;
    else          g_bc[j] = acc;
}

// ---------------------------------------------------------------------------
// K2: per-batch counting sort of edges by row (histogram + scan + scatter)
// ---------------------------------------------------------------------------
__global__ __launch_bounds__(1024) void k2_sort(const int* __restrict__ row,
                                                const int* __restrict__ col,
                                                const float* __restrict__ val) {
    __shared__ int bins[N_];
    __shared__ int sA[N_];
    int b = blockIdx.x, tid = threadIdx.x;
    bins[tid] = 0;
    __syncthreads();
    const int* rb = row + b * E_;
    const int* cb = col + b * E_;
    const float* vb = val + b * E_;
    for (int e = tid; e < E_; e += 1024) atomicAdd(&bins[rb[e]], 1);
    __syncthreads();
    int cnt = bins[tid];
    sA[tid] = cnt;
    __syncthreads();
    for (int off = 1; off < N_; off <<= 1) {
        int t = (tid >= off) ? sA[tid - off] : 0;
        __syncthreads();
        sA[tid] += t;
        __syncthreads();
    }
    int excl = sA[tid] - cnt;
    g_soff[b * (N_ + 1) + tid] = excl;
    if (tid == 0) g_soff[b * (N_ + 1) + N_] = E_;
    bins[tid] = excl;
    __syncthreads();
    for (int e = tid; e < E_; e += 1024) {
        int r = rb[e];
        int pos = atomicAdd(&bins[r], 1);
        g_scol[b * E_ + pos] = cb[e];
        g_sval[b * E_ + pos] = vb[e];
    }
}

// ---------------------------------------------------------------------------
// K3: seq[b,r,:] = sum_e val * emb[neighbors[b, col_e], :]   (pure spmm)
// one warp per (b, row); lane l<25 owns dims [4l,4l+4) via LDG.128. [R12]
// ---------------------------------------------------------------------------
__global__ __launch_bounds__(256) void k3_agg(const float* __restrict__ emb,
                                              const int* __restrict__ nbr) {
    int b = blockIdx.x;
    int rbase = blockIdx.y * 64;
    int warp = threadIdx.x >> 5, lane = threadIdx.x & 31;
    const int* sc = g_scol + b * E_;
    const float* sv = g_sval + b * E_;
    const int* nb = nbr + b * N_;
    bool ld = lane < 25;
    for (int r = rbase + warp; r < rbase + 64; r += 8) {
        int beg = g_soff[b * (N_ + 1) + r], end = g_soff[b * (N_ + 1) + r + 1];
        float4 acc0 = make_float4(0.f, 0.f, 0.f, 0.f);
        float4 acc1 = make_float4(0.f, 0.f, 0.f, 0.f);
        for (int ch = beg; ch < end; ch += 32) {
            int e = ch + lane;
            int cc = 0; float vv = 0.f;
            if (e < end) { cc = sc[e]; vv = sv[e]; }
            int ent = nb[cc];
            int cnt = min(32, end - ch);
            int i = 0;
            for (; i + 3 < cnt; i += 4) {
                int e0 = __shfl_sync(0xffffffffu, ent, i);
                int e1 = __shfl_sync(0xffffffffu, ent, i + 1);
                int e2 = __shfl_sync(0xffffffffu, ent, i + 2);
                int e3 = __shfl_sync(0xffffffffu, ent, i + 3);
                float v0 = __shfl_sync(0xffffffffu, vv, i);
                float v1 = __shfl_sync(0xffffffffu, vv, i + 1);
                float v2 = __shfl_sync(0xffffffffu, vv, i + 2);
                float v3 = __shfl_sync(0xffffffffu, vv, i + 3);
                if (ld) {
                    float4 x0 = *(const float4*)(emb + (size_t)e0 * HID_ + 4 * lane);
                    float4 x1 = *(const float4*)(emb + (size_t)e1 * HID_ + 4 * lane);
                    float4 x2 = *(const float4*)(emb + (size_t)e2 * HID_ + 4 * lane);
                    float4 x3 = *(const float4*)(emb + (size_t)e3 * HID_ + 4 * lane);
                    acc0.x += v0 * x0.x; acc0.y += v0 * x0.y; acc0.z += v0 * x0.z; acc0.w += v0 * x0.w;
                    acc1.x += v1 * x1.x; acc1.y += v1 * x1.y; acc1.z += v1 * x1.z; acc1.w += v1 * x1.w;
                    acc0.x += v2 * x2.x; acc0.y += v2 * x2.y; acc0.z += v2 * x2.z; acc0.w += v2 * x2.w;
                    acc1.x += v3 * x3.x; acc1.y += v3 * x3.y; acc1.z += v3 * x3.z; acc1.w += v3 * x3.w;
                }
            }
            for (; i < cnt; i++) {
                int e0 = __shfl_sync(0xffffffffu, ent, i);
                float v0 = __shfl_sync(0xffffffffu, vv, i);
                if (ld) {
                    float4 x0 = *(const float4*)(emb + (size_t)e0 * HID_ + 4 * lane);
                    acc0.x += v0 * x0.x; acc0.y += v0 * x0.y; acc0.z += v0 * x0.z; acc0.w += v0 * x0.w;
                }
            }
        }
        if (ld) {
            float4 o;
            o.x = acc0.x + acc1.x;
            o.y = acc0.y + acc1.y;
            o.z = acc0.z + acc1.z;
            o.w = acc0.w + acc1.w;
            *(float4*)(g_seq + (size_t)(b * N_ + r) * HID_ + 4 * lane) = o;
        }
    }
}

// ---------------------------------------------------------------------------
// K45: fused GX-GEMM + GRU recurrence. One block (608 thr, 19 warps) per batch.
// 32 chunks of 32 steps: stage X = seq[b, 32c:32c+32) as paired tf32, compute
// GXc = X @ Wc + bc with m16n8k8 (19 warps x 2 n-tiles x 2 m-passes) into
// smem, then run 32 recurrence steps reading gx from GXc. GX never touches
// DRAM. Recurrence: k-SPLIT x2 (thread = (k-half q, gate j)), HW tanh.approx.
// smem: Wcs[304*104] tf32 + Xs[32*104] + GXc[32*304] + bcs + hbuf + ps = 183KB.
// ---------------------------------------------------------------------------
#define K45_SMEM ((304 * 104 + 32 * 104) * 4 + (32 * 304 + 304 + 256 + 2 * 304) * 4)

__global__ __launch_bounds__(608) void k45_gru(const float* __restrict__ w_hh,
                                               const float* __restrict__ b_hh,
                                               const float* __restrict__ fc1_w,
                                               const float* __restrict__ fc1_b,
                                               float* __restrict__ out) {
    extern __shared__ u32 smem[];
    u32* Wcs = smem;                          // [304][104] tf32 paired
    u32* Xs  = smem + 304 * 104;              // [32][104]  tf32 paired
    float* fb = (float*)smem;
    float* GXc  = fb + 304 * 104 + 32 * 104;  // [32][304]
    float* bcs  = GXc + 32 * 304;             // [304]
    float* hbuf = bcs + 304;                  // [2][128], 16B-aligned
    float* ps   = hbuf + 256;                 // [2][304]

    int b = blockIdx.x, tid = threadIdx.x;
    int w = tid >> 5, lane = tid & 31;
    int g = lane >> 2, tig = lane & 3;
    int col0 = w * 16;                        // chunk-gemm: warp owns cols [col0, col0+16)

    int q = tid / 304;                        // recurrence k-half
    int j = tid % 304;                        // gate index, <300 active
    bool act = j < G3;
    u64 w2[26];
    if (act) {
        #pragma unroll
        for (int p = 0; p < 26; p++) {
            int k = 52 * q + 2 * p;
            w2[p] = (k + 1 < HID_) ? *(const u64*)(w_hh + j * HID_ + k) : 0ull;
        }
    }
    float br = 0.f, bz = 0.f, bn = 0.f;
    if (tid < HID_) {
        br = b_hh[tid]; bz = b_hh[HID_ + tid]; bn = b_hh[2 * HID_ + tid];
    }
    if (tid < 128) { hbuf[tid] = 0.f; hbuf[128 + tid] = 0.f; }

    // Stage Wc (k-major [100][300]) as paired tf32, rows = output cols
    for (int i = tid; i < 304 * 104; i += 608) {
        int n = i / 104, k = i % 104;
        float v = (n < G3 && k < HID_) ? g_Wc[k * G3 + n] : 0.f;
        Wcs[n * 104 + kidx(k)] = f2tf(v);
    }
    for (int i = tid; i < 304; i += 608)
        bcs[i] = (i < G3) ? g_bc[i] : 0.f;
    __syncthreads();

    const float4* seq4 = (const float4*)(g_seq + (size_t)b * N_ * HID_);

    for (int ch = 0; ch < 32; ch++) {
        // ---- stage X chunk (32 rows) ----
        for (int i = tid; i < 32 * 26; i += 608) {
            int m = i / 26, cc = i % 26;
            u32* rowp = Xs + m * 104;
            if (cc < 25) {
                float4 v = seq4[(size_t)(ch * 32 + m) * 25 + cc];
                int base = ((cc >> 1) << 3) + (cc & 1);
                rowp[base]     = f2tf(v.x);
                rowp[base + 2] = f2tf(v.y);
                rowp[base + 4] = f2tf(v.z);
                rowp[base + 6] = f2tf(v.w);
            } else {
                rowp[97] = 0u; rowp[99] = 0u; rowp[101] = 0u; rowp[103] = 0u;
            }
        }
        __syncthreads();

        // ---- chunk gemm: GXc = X @ Wc + bc ----
        #pragma unroll
        for (int mp = 0; mp < 2; mp++) {
            float cf0[4] = {0.f, 0.f, 0.f, 0.f};
            float cf1[4] = {0.f, 0.f, 0.f, 0.f};
            const u32* Xb = Xs + (mp * 16) * 104;
            #pragma unroll
            for (int ks = 0; ks < 13; ks++) {
                int k0 = ks * 8 + 2 * tig;
                uint2 a0 = *(const uint2*)&Xb[g * 104 + k0];
                uint2 a1 = *(const uint2*)&Xb[(g + 8) * 104 + k0];
                uint2 b0 = *(const uint2*)&Wcs[(col0 + g) * 104 + k0];
                uint2 b1 = *(const uint2*)&Wcs[(col0 + 8 + g) * 104 + k0];
                mma1688(cf0, a0.x, a1.x, a0.y, a1.y, b0.x, b0.y);
                mma1688(cf1, a0.x, a1.x, a0.y, a1.y, b1.x, b1.y);
            }
            int r = mp * 16 + g;
            int c0 = col0 + 2 * tig;
            int c1 = col0 + 8 + 2 * tig;
            GXc[r * 304 + c0]           = cf0[0] + bcs[c0];
            GXc[r * 304 + c0 + 1]       = cf0[1] + bcs[c0 + 1];
            GXc[(r + 8) * 304 + c0]     = cf0[2] + bcs[c0];
            GXc[(r + 8) * 304 + c0 + 1] = cf0[3] + bcs[c0 + 1];
            GXc[r * 304 + c1]           = cf1[0] + bcs[c1];
            GXc[r * 304 + c1 + 1]       = cf1[1] + bcs[c1 + 1];
            GXc[(r + 8) * 304 + c1]     = cf1[2] + bcs[c1];
            GXc[(r + 8) * 304 + c1 + 1] = cf1[3] + bcs[c1 + 1];
        }
        __syncthreads();   // GXc ready; also orders hbuf for first step

        // ---- 32 recurrence steps ----
        for (int tt = 0; tt < 32; tt++) {
            int t = ch * 32 + tt;
            const float* hc = hbuf + (t & 1) * 128;
            if (act) {
                const ulonglong2* hp = (const ulonglong2*)(hc + 52 * q);
                u64 a0 = 0, a1 = 0, a2 = 0, a3 = 0;
                #pragma unroll
                for (int cc = 0; cc < 13; cc++) {
                    ulonglong2 hv = hp[cc];
                    if (cc & 1) { ffma2(a2, w2[2 * cc], hv.x); ffma2(a3, w2[2 * cc + 1], hv.y); }
                    else        { ffma2(a0, w2[2 * cc], hv.x); ffma2(a1, w2[2 * cc + 1], hv.y); }
                }
                ps[q * 304 + j] = sum2(a0) + sum2(a1) + sum2(a2) + sum2(a3);
            }
            __syncthreads();                 // partials ready
            if (tid < HID_) {
                const float* gx = GXc + tt * 304;
                float gxr = gx[tid], gxz = gx[HID_ + tid], gxn = gx[2 * HID_ + tid];
                float hr = ps[tid] + ps[304 + tid] + br;
                float hz = ps[HID_ + tid] + ps[304 + HID_ + tid] + bz;
                float hn = ps[2 * HID_ + tid] + ps[304 + 2 * HID_ + tid] + bn;
                float r = 0.5f * tanhapx(0.5f * (gxr + hr)) + 0.5f;
                float z = 0.5f * tanhapx(0.5f * (gxz + hz)) + 0.5f;
                float n = tanhapx(gxn + r * hn);
                hbuf[((t + 1) & 1) * 128 + tid] = (1.f - z) * n + z * hc[tid];
            }
            __syncthreads();                 // h(t+1) ready; ps WAR protected
        }
        // chunk-top WAR on Xs/GXc is covered by the last step's trailing barrier
    }

    if (tid < HID_) {
        const float* hf = hbuf;              // t=1023 wrote buffer 0
        float acc = fc1_b[tid];
        const float* wr = fc1_w + tid * HID_;
        #pragma unroll
        for (int k = 0; k < HID_; k++) acc += hf[k] * wr[k];
        out[b * HID_ + tid] = fmaxf(acc, 0.f);
    }
}

// ---------------------------------------------------------------------------
extern "C" void kernel_launch(void* const* d_in, const int* in_sizes, int n_in,
                              void* d_out, int out_size) {
    const int*   neighbors = (const int*)d_in[0];
    const int*   adj_row   = (const int*)d_in[1];
    const int*   adj_col   = (const int*)d_in[2];
    const float* adj_val   = (const float*)d_in[3];
    const float* emb       = (const float*)d_in[4];
    const float* gcn_w     = (const float*)d_in[5];
    const float* gcn_b     = (const float*)d_in[6];
    const float* w_ih      = (const float*)d_in[7];
    const float* w_hh      = (const float*)d_in[8];
    const float* b_ih      = (const float*)d_in[9];
    const float* b_hh      = (const float*)d_in[10];
    const float* fc1_w     = (const float*)d_in[11];
    const float* fc1_b     = (const float*)d_in[12];
    float* out = (float*)d_out;

    cudaFuncSetAttribute(k45_gru, cudaFuncAttributeMaxDynamicSharedMemorySize, K45_SMEM);

    // K0: fold gcn_w/gcn_b through w_ih/b_ih  -> g_Wc, g_bc
    k0_fold<<<HID_ + 1, G3>>>(gcn_w, gcn_b, w_ih, b_ih);
    // K2: sort edges by row
    k2_sort<<<B_, 1024>>>(adj_row, adj_col, adj_val);
    // K3: pure spmm over raw embeddings
    k3_agg <<<dim3(B_, 16), 256>>>(emb, neighbors);
    // K45: fused GX-gemm + GRU recurrence + FC
    k45_gru<<<B_, 608, K45_SMEM>>>(w_hh, b_hh, fc1_w, fc1_b, out);
}

// round 14
// speedup vs baseline: 1.7452x; 1.0380x over previous
#include <cuda_runtime.h>

#define B_ 128
#define N_ 1024
#define E_ 16384
#define ENTITY_ 100000
#define HID_ 100
#define G3 300

// Scratch (static __device__ per harness rules; no runtime allocation)
__device__ float g_seq[B_ * N_ * HID_];      // spmm(emb[nbr])      (52MB)
__device__ float g_Wc[HID_ * G3];            // gcn_w @ w_ih^T  [100][300] k-major
__device__ float g_bc[G3];                   // w_ih @ gcn_b + b_ih
__device__ int   g_soff[B_ * (N_ + 1)];
__device__ int   g_scol[B_ * E_];
__device__ float g_sval[B_ * E_];

typedef unsigned long long u64;
typedef unsigned int u32;

__device__ __forceinline__ void ffma2(u64 &acc, u64 a, u64 b) {
    asm("fma.rn.f32x2 %0, %1, %2, %0;" : "+l"(acc) : "l"(a), "l"(b));
}
__device__ __forceinline__ u64 pk2(float lo, float hi) {
    u64 r; asm("mov.b64 %0, {%1, %2};" : "=l"(r) : "f"(lo), "f"(hi)); return r;
}
__device__ __forceinline__ float sum2(u64 v) {
    float lo, hi; asm("mov.b64 {%0, %1}, %2;" : "=f"(lo), "=f"(hi) : "l"(v)); return lo + hi;
}
__device__ __forceinline__ u32 f2tf(float x) {
    u32 r; asm("cvt.rna.tf32.f32 %0, %1;" : "=r"(r) : "f"(x)); return r;
}
__device__ __forceinline__ float tanhapx(float x) {
    float r; asm("tanh.approx.f32 %0, %1;" : "=f"(r) : "f"(x)); return r;
}
__device__ __forceinline__ void mma1688(float c[4], u32 a0, u32 a1, u32 a2, u32 a3,
                                        u32 b0, u32 b1) {
    asm("mma.sync.aligned.m16n8k8.row.col.f32.tf32.tf32.f32 "
        "{%0,%1,%2,%3}, {%4,%5,%6,%7}, {%8,%9}, {%0,%1,%2,%3};"
        : "+f"(c[0]), "+f"(c[1]), "+f"(c[2]), "+f"(c[3])
        : "r"(a0), "r"(a1), "r"(a2), "r"(a3), "r"(b0), "r"(b1));
}

__device__ __forceinline__ int kidx(int k) {   // paired index within a 104-k row
    return ((k >> 3) << 3) + ((k & 3) << 1) + ((k & 7) >> 2);
}

// ---------------------------------------------------------------------------
// K0: fold the GCN weights through the GRU input projection (fp32).
// ---------------------------------------------------------------------------
__global__ __launch_bounds__(G3) void k0_fold(const float* __restrict__ gcn_w,
                                              const float* __restrict__ gcn_b,
                                              const float* __restrict__ w_ih,
                                              const float* __restrict__ b_ih) {
    __shared__ float xs[HID_];
    int j = threadIdx.x;
    int e = blockIdx.x;
    const float* src = (e < HID_) ? (gcn_w + e * HID_) : gcn_b;
    if (j < HID_) xs[j] = src[j];
    __syncthreads();
    float acc = (e < HID_) ? 0.f : b_ih[j];
    const float* wr = w_ih + j * HID_;
    #pragma unroll
    for (int h = 0; h < HID_; h++) acc += xs[h] * wr[h];
    if (e < HID_) g_Wc[e * G3 + j] = acc;
    else          g_bc[j] = acc;
}

// ---------------------------------------------------------------------------
// K2: per-batch counting sort of edges by row (histogram + scan + scatter)
// ---------------------------------------------------------------------------
__global__ __launch_bounds__(1024) void k2_sort(const int* __restrict__ row,
                                                const int* __restrict__ col,
                                                const float* __restrict__ val) {
    __shared__ int bins[N_];
    __shared__ int sA[N_];
    int b = blockIdx.x, tid = threadIdx.x;
    bins[tid] = 0;
    __syncthreads();
    const int* rb = row + b * E_;
    const int* cb = col + b * E_;
    const float* vb = val + b * E_;
    for (int e = tid; e < E_; e += 1024) atomicAdd(&bins[rb[e]], 1);
    __syncthreads();
    int cnt = bins[tid];
    sA[tid] = cnt;
    __syncthreads();
    for (int off = 1; off < N_; off <<= 1) {
        int t = (tid >= off) ? sA[tid - off] : 0;
        __syncthreads();
        sA[tid] += t;
        __syncthreads();
    }
    int excl = sA[tid] - cnt;
    g_soff[b * (N_ + 1) + tid] = excl;
    if (tid == 0) g_soff[b * (N_ + 1) + N_] = E_;
    bins[tid] = excl;
    __syncthreads();
    for (int e = tid; e < E_; e += 1024) {
        int r = rb[e];
        int pos = atomicAdd(&bins[r], 1);
        g_scol[b * E_ + pos] = cb[e];
        g_sval[b * E_ + pos] = vb[e];
    }
}

// ---------------------------------------------------------------------------
// K3: seq[b,r,:] = sum_e val * emb[neighbors[b, col_e], :]   (pure spmm)
// ---------------------------------------------------------------------------
__global__ __launch_bounds__(256) void k3_agg(const float* __restrict__ emb,
                                              const int* __restrict__ nbr) {
    int b = blockIdx.x;
    int rbase = blockIdx.y * 64;
    int warp = threadIdx.x >> 5, lane = threadIdx.x & 31;
    const int* sc = g_scol + b * E_;
    const float* sv = g_sval + b * E_;
    const int* nb = nbr + b * N_;
    bool ld = lane < 25;
    for (int r = rbase + warp; r < rbase + 64; r += 8) {
        int beg = g_soff[b * (N_ + 1) + r], end = g_soff[b * (N_ + 1) + r + 1];
        float4 acc0 = make_float4(0.f, 0.f, 0.f, 0.f);
        float4 acc1 = make_float4(0.f, 0.f, 0.f, 0.f);
        for (int ch = beg; ch < end; ch += 32) {
            int e = ch + lane;
            int cc = 0; float vv = 0.f;
            if (e < end) { cc = sc[e]; vv = sv[e]; }
            int ent = nb[cc];
            int cnt = min(32, end - ch);
            int i = 0;
            for (; i + 3 < cnt; i += 4) {
                int e0 = __shfl_sync(0xffffffffu, ent, i);
                int e1 = __shfl_sync(0xffffffffu, ent, i + 1);
                int e2 = __shfl_sync(0xffffffffu, ent, i + 2);
                int e3 = __shfl_sync(0xffffffffu, ent, i + 3);
                float v0 = __shfl_sync(0xffffffffu, vv, i);
                float v1 = __shfl_sync(0xffffffffu, vv, i + 1);
                float v2 = __shfl_sync(0xffffffffu, vv, i + 2);
                float v3 = __shfl_sync(0xffffffffu, vv, i + 3);
                if (ld) {
                    float4 x0 = *(const float4*)(emb + (size_t)e0 * HID_ + 4 * lane);
                    float4 x1 = *(const float4*)(emb + (size_t)e1 * HID_ + 4 * lane);
                    float4 x2 = *(const float4*)(emb + (size_t)e2 * HID_ + 4 * lane);
                    float4 x3 = *(const float4*)(emb + (size_t)e3 * HID_ + 4 * lane);
                    acc0.x += v0 * x0.x; acc0.y += v0 * x0.y; acc0.z += v0 * x0.z; acc0.w += v0 * x0.w;
                    acc1.x += v1 * x1.x; acc1.y += v1 * x1.y; acc1.z += v1 * x1.z; acc1.w += v1 * x1.w;
                    acc0.x += v2 * x2.x; acc0.y += v2 * x2.y; acc0.z += v2 * x2.z; acc0.w += v2 * x2.w;
                    acc1.x += v3 * x3.x; acc1.y += v3 * x3.y; acc1.z += v3 * x3.z; acc1.w += v3 * x3.w;
                }
            }
            for (; i < cnt; i++) {
                int e0 = __shfl_sync(0xffffffffu, ent, i);
                float v0 = __shfl_sync(0xffffffffu, vv, i);
                if (ld) {
                    float4 x0 = *(const float4*)(emb + (size_t)e0 * HID_ + 4 * lane);
                    acc0.x += v0 * x0.x; acc0.y += v0 * x0.y; acc0.z += v0 * x0.z; acc0.w += v0 * x0.w;
                }
            }
        }
        if (ld) {
            float4 o;
            o.x = acc0.x + acc1.x;
            o.y = acc0.y + acc1.y;
            o.z = acc0.z + acc1.z;
            o.w = acc0.w + acc1.w;
            *(float4*)(g_seq + (size_t)(b * N_ + r) * HID_ + 4 * lane) = o;
        }
    }
}

// ---------------------------------------------------------------------------
// K45: fused GX-GEMM + GRU recurrence. One block (608 thr) per batch.
// Chunk-gemm (unchanged, m16n8k8). Recurrence re-mapped: thread = (k-eighth
// q=tid&7, 4 gates g0=(tid>>3)*4), 600 active. h stored in eighth-padded
// layout hq[2][8][20] (13 live + pad; eighth bases hit disjoint banks) ->
// each thread loads only 4 LDS.128 per step serving 4 gates: h-broadcast
// wavefronts drop 988 -> ~300 cyc/step. Partials in ps[8][308]; activation
// (100 thr) combines 8, applies HW tanh gates, writes h.
// ---------------------------------------------------------------------------
#define K45_SMEM ((304 * 104 + 32 * 104) * 4 + (32 * 304 + 304 + 320 + 8 * 308) * 4)

__global__ __launch_bounds__(608) void k45_gru(const float* __restrict__ w_hh,
                                               const float* __restrict__ b_hh,
                                               const float* __restrict__ fc1_w,
                                               const float* __restrict__ fc1_b,
                                               float* __restrict__ out) {
    extern __shared__ u32 smem[];
    u32* Wcs = smem;                          // [304][104] tf32 paired
    u32* Xs  = smem + 304 * 104;              // [32][104]  tf32 paired
    float* fb = (float*)smem;
    float* GXc  = fb + 304 * 104 + 32 * 104;  // [32][304]
    float* bcs  = GXc + 32 * 304;             // [304]
    float* hq   = bcs + 304;                  // [2][8][20] eighth-padded h
    float* ps   = hq + 320;                   // [8][308]

    int b = blockIdx.x, tid = threadIdx.x;
    int w = tid >> 5, lane = tid & 31;
    int g = lane >> 2, tig = lane & 3;
    int col0 = w * 16;                        // chunk-gemm warp cols

    // recurrence mapping
    bool ghact = tid < 600;
    int q8 = tid & 7;                         // k-eighth: k in [13*q8, 13*q8+13)
    int g0 = (tid >> 3) << 2;                 // 4 gates g0..g0+3  (<300)

    u64 w2[4][7];
    if (ghact) {
        #pragma unroll
        for (int gg = 0; gg < 4; gg++) {
            const float* wr = w_hh + (g0 + gg) * HID_;
            #pragma unroll
            for (int p = 0; p < 7; p++) {
                int k = 13 * q8 + 2 * p;
                float lo = (k < HID_) ? wr[k] : 0.f;
                float hi = (2 * p + 1 < 13 && k + 1 < HID_) ? wr[k + 1] : 0.f;
                w2[gg][p] = pk2(lo, hi);
            }
        }
    }
    float br = 0.f, bz = 0.f, bn = 0.f;
    int dh = 0, mh = 0;
    if (tid < HID_) {
        br = b_hh[tid]; bz = b_hh[HID_ + tid]; bn = b_hh[2 * HID_ + tid];
        dh = tid / 13; mh = tid - dh * 13;
    }
    for (int i = tid; i < 320; i += 608) hq[i] = 0.f;   // zero h + pads

    // Stage Wc (k-major [100][300]) as paired tf32
    for (int i = tid; i < 304 * 104; i += 608) {
        int n = i / 104, k = i % 104;
        float v = (n < G3 && k < HID_) ? g_Wc[k * G3 + n] : 0.f;
        Wcs[n * 104 + kidx(k)] = f2tf(v);
    }
    for (int i = tid; i < 304; i += 608)
        bcs[i] = (i < G3) ? g_bc[i] : 0.f;
    __syncthreads();

    const float4* seq4 = (const float4*)(g_seq + (size_t)b * N_ * HID_);

    for (int ch = 0; ch < 32; ch++) {
        // ---- stage X chunk (32 rows) ----
        for (int i = tid; i < 32 * 26; i += 608) {
            int m = i / 26, cc = i % 26;
            u32* rowp = Xs + m * 104;
            if (cc < 25) {
                float4 v = seq4[(size_t)(ch * 32 + m) * 25 + cc];
                int base = ((cc >> 1) << 3) + (cc & 1);
                rowp[base]     = f2tf(v.x);
                rowp[base + 2] = f2tf(v.y);
                rowp[base + 4] = f2tf(v.z);
                rowp[base + 6] = f2tf(v.w);
            } else {
                rowp[97] = 0u; rowp[99] = 0u; rowp[101] = 0u; rowp[103] = 0u;
            }
        }
        __syncthreads();

        // ---- chunk gemm: GXc = X @ Wc + bc ----
        #pragma unroll
        for (int mp = 0; mp < 2; mp++) {
            float cf0[4] = {0.f, 0.f, 0.f, 0.f};
            float cf1[4] = {0.f, 0.f, 0.f, 0.f};
            const u32* Xb = Xs + (mp * 16) * 104;
            #pragma unroll
            for (int ks = 0; ks < 13; ks++) {
                int k0 = ks * 8 + 2 * tig;
                uint2 a0 = *(const uint2*)&Xb[g * 104 + k0];
                uint2 a1 = *(const uint2*)&Xb[(g + 8) * 104 + k0];
                uint2 b0 = *(const uint2*)&Wcs[(col0 + g) * 104 + k0];
                uint2 b1 = *(const uint2*)&Wcs[(col0 + 8 + g) * 104 + k0];
                mma1688(cf0, a0.x, a1.x, a0.y, a1.y, b0.x, b0.y);
                mma1688(cf1, a0.x, a1.x, a0.y, a1.y, b1.x, b1.y);
            }
            int r = mp * 16 + g;
            int c0 = col0 + 2 * tig;
            int c1 = col0 + 8 + 2 * tig;
            GXc[r * 304 + c0]           = cf0[0] + bcs[c0];
            GXc[r * 304 + c0 + 1]       = cf0[1] + bcs[c0 + 1];
            GXc[(r + 8) * 304 + c0]     = cf0[2] + bcs[c0];
            GXc[(r + 8) * 304 + c0 + 1] = cf0[3] + bcs[c0 + 1];
            GXc[r * 304 + c1]           = cf1[0] + bcs[c1];
            GXc[r * 304 + c1 + 1]       = cf1[1] + bcs[c1 + 1];
            GXc[(r + 8) * 304 + c1]     = cf1[2] + bcs[c1];
            GXc[(r + 8) * 304 + c1 + 1] = cf1[3] + bcs[c1 + 1];
        }
        __syncthreads();   // GXc ready

        // ---- 32 recurrence steps ----
        for (int tt = 0; tt < 32; tt++) {
            int t = ch * 32 + tt;
            int cur = t & 1;
            if (ghact) {
                const float* hb = hq + cur * 160 + q8 * 20;
                ulonglong2 u0 = *(const ulonglong2*)(hb);
                ulonglong2 u1 = *(const ulonglong2*)(hb + 4);
                ulonglong2 u2 = *(const ulonglong2*)(hb + 8);
                ulonglong2 u3 = *(const ulonglong2*)(hb + 12);
                float4 sv;
                float* svp = &sv.x;
                #pragma unroll
                for (int gg = 0; gg < 4; gg++) {
                    u64 a0 = 0, a1 = 0;
                    ffma2(a0, w2[gg][0], u0.x);
                    ffma2(a1, w2[gg][1], u0.y);
                    ffma2(a0, w2[gg][2], u1.x);
                    ffma2(a1, w2[gg][3], u1.y);
                    ffma2(a0, w2[gg][4], u2.x);
                    ffma2(a1, w2[gg][5], u2.y);
                    ffma2(a0, w2[gg][6], u3.x);
                    svp[gg] = sum2(a0) + sum2(a1);
                }
                *(float4*)(ps + q8 * 308 + g0) = sv;
            }
            __syncthreads();                 // partials ready
            if (tid < HID_) {
                const float* gx = GXc + tt * 304;
                float hr = br, hz = bz, hn = bn;
                #pragma unroll
                for (int qq = 0; qq < 8; qq++) {
                    const float* pr = ps + qq * 308;
                    hr += pr[tid];
                    hz += pr[HID_ + tid];
                    hn += pr[2 * HID_ + tid];
                }
                float gxr = gx[tid], gxz = gx[HID_ + tid], gxn = gx[2 * HID_ + tid];
                float r = 0.5f * tanhapx(0.5f * (gxr + hr)) + 0.5f;
                float z = 0.5f * tanhapx(0.5f * (gxz + hz)) + 0.5f;
                float n = tanhapx(gxn + r * hn);
                float hcur = hq[cur * 160 + dh * 20 + mh];
                hq[(cur ^ 1) * 160 + dh * 20 + mh] = (1.f - z) * n + z * hcur;
            }
            __syncthreads();                 // h(t+1) ready; ps WAR protected
        }
    }

    if (tid < HID_) {
        float acc = fc1_b[tid];
        const float* wr = fc1_w + tid * HID_;
        #pragma unroll
        for (int k = 0; k < HID_; k++) {
            int dq = k / 13, mq = k - dq * 13;
            acc += hq[dq * 20 + mq] * wr[k];     // final h lives in buffer 0
        }
        out[b * HID_ + tid] = fmaxf(acc, 0.f);
    }
}

// ---------------------------------------------------------------------------
extern "C" void kernel_launch(void* const* d_in, const int* in_sizes, int n_in,
                              void* d_out, int out_size) {
    const int*   neighbors = (const int*)d_in[0];
    const int*   adj_row   = (const int*)d_in[1];
    const int*   adj_col   = (const int*)d_in[2];
    const float* adj_val   = (const float*)d_in[3];
    const float* emb       = (const float*)d_in[4];
    const float* gcn_w     = (const float*)d_in[5];
    const float* gcn_b     = (const float*)d_in[6];
    const float* w_ih      = (const float*)d_in[7];
    const float* w_hh      = (const float*)d_in[8];
    const float* b_ih      = (const float*)d_in[9];
    const float* b_hh      = (const float*)d_in[10];
    const float* fc1_w     = (const float*)d_in[11];
    const float* fc1_b     = (const float*)d_in[12];
    float* out = (float*)d_out;

    cudaFuncSetAttribute(k45_gru, cudaFuncAttributeMaxDynamicSharedMemorySize, K45_SMEM);

    // K0: fold gcn_w/gcn_b through w_ih/b_ih  -> g_Wc, g_bc
    k0_fold<<<HID_ + 1, G3>>>(gcn_w, gcn_b, w_ih, b_ih);
    // K2: sort edges by row
    k2_sort<<<B_, 1024>>>(adj_row, adj_col, adj_val);
    // K3: pure spmm over raw embeddings
    k3_agg <<<dim3(B_, 16), 256>>>(emb, neighbors);
    // K45: fused GX-gemm + GRU recurrence + FC
    k45_gru<<<B_, 608, K45_SMEM>>>(w_hh, b_hh, fc1_w, fc1_b, out);
}